// round 9
// baseline (speedup 1.0000x reference)
#include <cuda_runtime.h>

#define KCH    32
#define HW     64
#define TSTEPS 100
#define PLANE  4096
#define NCTA   128
#define NTHR   512
#define ROWS_L 60
#define RP     65

// Double-buffered recurrent state X_t. Step t reads g_state[t&1], writes g_state[(t+1)&1].
__device__ float g_state[2][2 * KCH * PLANE];

// Flag-array barrier: each CTA release-stores a monotonically increasing step
// count to its own flag (no atomics, no same-address serialization). CTA 0
// aggregates all 128 flags (1 poller thread per flag) and release-stores the
// generation. All values are monotonic across graph replays; only relative
// compares are used, and every CTA performs the same number of stores per
// replay, so bases stay globally uniform.
__device__ unsigned g_bar_gen;
__device__ unsigned g_flags[NCTA];

__device__ __forceinline__ unsigned ld_acq(const unsigned* p) {
    unsigned v;
    asm volatile("ld.acquire.gpu.global.u32 %0, [%1];" : "=r"(v) : "l"(p) : "memory");
    return v;
}
__device__ __forceinline__ void st_rel(unsigned* p, unsigned v) {
    asm volatile("st.release.gpu.global.u32 [%0], %1;" :: "l"(p), "r"(v) : "memory");
}

__global__ void __launch_bounds__(NTHR, 1)
persist_kernel(const float* __restrict__ inbound,
               const float* __restrict__ Wf,
               const float* __restrict__ bf,
               const float* __restrict__ Ws,
               const float* __restrict__ bs,
               float* __restrict__ out)
{
    extern __shared__ float sm[];
    float* Rb0 = sm;                           // [60][65] X halo rows (even t)
    float* Rb1 = Rb0 + ROWS_L * RP;            // [60][65] X halo rows (odd t)
    float* H29 = Rb1 + ROWS_L * RP;            // [60][65] 29-wide horizontal sums
    float* H9  = H29 + ROWS_L * RP;            // [60][65] 9-wide horizontal sums
    float* S   = H9  + ROWS_L * RP;            // [32][64] feat + 0.5*inb + bf
    float* WfS = S + 32 * HW;
    __shared__ unsigned sb[2];

    const int b   = blockIdx.x;                // 0..127
    const int tid = threadIdx.x;
    const int n   = b >> 6;
    const int k   = (b & 63) >> 1;
    const int h   = b & 1;
    const int r0  = h << 5;
    const int partner = b ^ 1;
    const size_t plane_off = (size_t)(n * KCH + k) * PLANE;

    if (tid < KCH) WfS[tid] = Wf[k * KCH + tid];
    if (tid == 0) { sb[0] = ld_acq(&g_bar_gen); sb[1] = ld_acq(&g_flags[b]); }

    const float bf_k = bf[k];
    const float bs_k = bs[k];
    const float inh  = Ws[k * 841];                 // uniform inhibition value
    const float emin = Ws[k * 841 + 420] - inh;     // center excitation minus inh

    // zero both R buffers + H29 + H9 (X_0 = 0; edge rows stay zero forever)
    for (int i = tid; i < 4 * ROWS_L * RP; i += NTHR) sm[i] = 0.f;

    // ---- feat mapping: (row rr_f, 4 contiguous pixels) ----
    const int rr_f = tid >> 4;                 // 0..31
    const int w0_f = (tid & 15) << 2;
    const float4 inb4 = *(const float4*)(inbound + plane_off + (r0 + rr_f) * HW + w0_f);
    const float base0 = 0.5f * inb4.x + bf_k;
    const float base1 = 0.5f * inb4.y + bf_k;
    const float base2 = 0.5f * inb4.z + bf_k;
    const float base3 = 0.5f * inb4.w + bf_k;
    *(float4*)&S[rr_f * HW + w0_f] = make_float4(base0, base1, base2, base3);

    // ---- partner-halo mapping: 14 rows x 16 float4 = 224 items ----
    // h=0: global rows 32..45 -> j=46..59 ; h=1: global rows 18..31 -> j=0..13
    const int pj0 = h ? 0 : 46;
    const int pg0 = h ? 18 : 32;
    const int jr  = tid >> 4;                  // valid for tid<224
    const int wq  = (tid & 15) << 2;

    // ---- H mapping ----
    const int j_h = tid >> 3;                  // 0..63 (active <60)
    const int s_h = (tid & 7) << 3;

    // ---- V mapping: 512 threads, (column, 4-row segment) ----
    const int w_v = tid & 63;
    const int rb  = (tid >> 6) << 2;

    __syncthreads();
    const unsigned gen0 = sb[0], fbase = sb[1];

    for (int t = 0; t < TSTEPS; t++) {
        float* R_cur = (t & 1) ? Rb1 : Rb0;
        float* R_nxt = (t & 1) ? Rb0 : Rb1;

        // ======== feat (t>0): S = base + Wf @ X_t ========
        if (t > 0) {
            const float4* bp = (const float4*)(g_state[t & 1]
                               + (size_t)n * KCH * PLANE + (r0 + rr_f) * HW + w0_f);
            float a0 = base0, a1 = base1, a2 = base2, a3 = base3;
            #pragma unroll
            for (int i = 0; i < KCH; i++) {
                const float wv = WfS[i];
                const float4 x = bp[i * (PLANE / 4)];
                a0 += wv * x.x; a1 += wv * x.y;
                a2 += wv * x.z; a3 += wv * x.w;
            }
            *(float4*)&S[rr_f * HW + w0_f] = make_float4(a0, a1, a2, a3);
            __syncthreads();
        }

        // ======== V: vertical box sums (H from previous tail) + combine ========
        float xn_s[4];
        {
            float b29a = 0.f, b29b = 0.f, b9 = 0.f;
            #pragma unroll
            for (int d = 0; d < 14; d++) {
                b29a += H29[(rb + d) * RP + w_v];
                b29b += H29[(rb + 14 + d) * RP + w_v];
            }
            float b29 = b29a + b29b + H29[(rb + 28) * RP + w_v];
            #pragma unroll
            for (int d = 0; d < 9; d++) b9 += H9[(rb + 10 + d) * RP + w_v];

            float* dst = g_state[(t + 1) & 1];
            #pragma unroll
            for (int r = 0; r < 4; r++) {
                const int rr = rb + r;
                const int j  = rr + 14;
                if (r > 0) {
                    b29 += H29[(rr + 28) * RP + w_v] - H29[(rr - 1) * RP + w_v];
                    b9  += H9 [(j + 4)  * RP + w_v] - H9 [(j - 5)  * RP + w_v];
                }
                const float sp = inh * b29 + emin * b9 + bs_k;
                const float xo = R_cur[j * RP + w_v];
                const float xn = 0.8f * xo + 0.2f * fmaxf(S[rr * HW + w_v] + sp, 0.f);
                xn_s[r] = xn;
                R_nxt[j * RP + w_v] = xn;                  // interior rows for t+1
                dst[plane_off + (size_t)(r0 + rr) * HW + w_v] = xn;
            }
        }

        const size_t outb = ((size_t)(n * TSTEPS + t) * KCH + k) * PLANE
                            + (size_t)(r0 + rb) * HW + w_v;
        if (t == TSTEPS - 1) {
            #pragma unroll
            for (int r = 0; r < 4; r++)
                out[outb + (size_t)r * HW] = xn_s[r];
            break;
        }

        __syncthreads();                       // dst/R_nxt stores + smem reads done
        const unsigned ftgt = fbase + (unsigned)t + 1u;
        const unsigned gtgt = gen0  + (unsigned)t + 1u;
        if (tid == 0) st_rel(&g_flags[b], ftgt);   // ARRIVE (release; no atomic)

        // out stores hidden in the barrier shadow
        #pragma unroll
        for (int r = 0; r < 4; r++)
            out[outb + (size_t)r * HW] = xn_s[r];

        if (b == 0) {
            // ---- aggregator: 128 pollers, one flag each; then release gen ----
            if (tid < NCTA) {
                while ((int)(ld_acq(&g_flags[tid]) - ftgt) < 0) { }
                asm volatile("bar.sync 1, 128;" ::: "memory");
                if (tid == 0) st_rel(&g_bar_gen, gtgt);
            }
        } else {
            // wait only for partner before touching its halo rows
            if (tid == 0) {
                while ((int)(ld_acq(&g_flags[partner]) - ftgt) < 0) { }
            }
        }
        __syncthreads();

        // ======== partner halo rows of X_{t+1} -> R_nxt (barrier shadow) ========
        if (tid < 224) {
            const float4 v = *(const float4*)(g_state[(t + 1) & 1] + plane_off
                                              + (pg0 + jr) * HW + wq);
            float* rp = &R_nxt[(pj0 + jr) * RP + wq];
            rp[0] = v.x; rp[1] = v.y; rp[2] = v.z; rp[3] = v.w;
        }
        __syncthreads();

        // ======== H for step t+1 from R_nxt (barrier shadow) ========
        if (j_h < ROWS_L) {
            float v[36];
            const float* row = &R_nxt[j_h * RP];
            #pragma unroll
            for (int d = 0; d < 36; d++) {
                const int w = s_h - 14 + d;
                v[d] = (w >= 0 && w < HW) ? row[w] : 0.f;
            }
            float sa = 0.f, sc = 0.f;
            #pragma unroll
            for (int d = 0; d < 14; d++) { sa += v[d]; sc += v[d + 14]; }
            float s29 = sa + sc + v[28];
            H29[j_h * RP + s_h] = s29;
            #pragma unroll
            for (int p = 1; p < 8; p++) {
                s29 += v[p + 28] - v[p - 1];
                H29[j_h * RP + s_h + p] = s29;
            }
            float s9 = 0.f;
            #pragma unroll
            for (int d = 10; d < 19; d++) s9 += v[d];
            H9[j_h * RP + s_h] = s9;
            #pragma unroll
            for (int p = 1; p < 8; p++) {
                s9 += v[p + 18] - v[p + 9];
                H9[j_h * RP + s_h + p] = s9;
            }
        }

        // full-barrier wait (CTA 0 released it itself; others mostly satisfied)
        if (b != 0 && tid == 0) {
            while ((int)(ld_acq(&g_bar_gen) - gtgt) < 0) { }
        }
        __syncthreads();
    }
}

extern "C" void kernel_launch(void* const* d_in, const int* in_sizes, int n_in,
                              void* d_out, int out_size)
{
    const float* inbound = (const float*)d_in[0];
    const float* Wf      = (const float*)d_in[1];
    const float* bf      = (const float*)d_in[2];
    const float* Ws      = (const float*)d_in[3];
    const float* bs      = (const float*)d_in[4];
    float* out = (float*)d_out;

    const int smem_bytes = (4 * ROWS_L * RP + 32 * HW + KCH) * sizeof(float) + 16;
    static bool attr_set = false;
    if (!attr_set) {
        cudaFuncSetAttribute(persist_kernel,
                             cudaFuncAttributeMaxDynamicSharedMemorySize, smem_bytes);
        attr_set = true;
    }
    persist_kernel<<<NCTA, NTHR, smem_bytes>>>(inbound, Wf, bf, Ws, bs, out);
}

// round 10
// speedup vs baseline: 1.8357x; 1.8357x over previous
#include <cuda_runtime.h>

#define KCH    32
#define HW     64
#define TSTEPS 100
#define PLANE  4096
#define NCTA   128
#define NCTA_B 64          // CTAs per batch (independent barrier groups)
#define NTHR   512
#define ROWS_L 60
#define RP     65

// State X_{t+1} lives directly in the output tensor out[n, t, k, :, :].
// Step t>0 reads X_t = out[n, t-1, :, :, :]; t==0 reads nothing (X_0 = 0).

// Per-batch barrier (R8 mechanism: atomicAdd arrive + gen release) + per-CTA
// partner flags. gen/flags monotonic across graph replays (relative compares
// only); cnt reset to 0 by each releaser.
__device__ unsigned g_bar_cnt[2], g_bar_gen[2];
__device__ unsigned g_flags[NCTA];

__device__ __forceinline__ unsigned ld_acq(const unsigned* p) {
    unsigned v;
    asm volatile("ld.acquire.gpu.global.u32 %0, [%1];" : "=r"(v) : "l"(p) : "memory");
    return v;
}
__device__ __forceinline__ void st_rel(unsigned* p, unsigned v) {
    asm volatile("st.release.gpu.global.u32 [%0], %1;" :: "l"(p), "r"(v) : "memory");
}

__global__ void __launch_bounds__(NTHR, 1)
persist_kernel(const float* __restrict__ inbound,
               const float* __restrict__ Wf,
               const float* __restrict__ bf,
               const float* __restrict__ Ws,
               const float* __restrict__ bs,
               float* __restrict__ out)
{
    extern __shared__ float sm[];
    float* Rb0 = sm;                           // [60][65] X halo rows (even t)
    float* Rb1 = Rb0 + ROWS_L * RP;            // [60][65] X halo rows (odd t)
    float* H29 = Rb1 + ROWS_L * RP;            // [60][65] 29-wide horizontal sums
    float* H9  = H29 + ROWS_L * RP;            // [60][65] 9-wide horizontal sums
    float* S   = H9  + ROWS_L * RP;            // [32][64] feat + 0.5*inb + bf
    float* WfS = S + 32 * HW;
    __shared__ unsigned sb[2];

    const int b   = blockIdx.x;                // 0..127
    const int tid = threadIdx.x;
    const int n   = b >> 6;
    const int k   = (b & 63) >> 1;
    const int h   = b & 1;
    const int r0  = h << 5;
    const int partner = b ^ 1;
    const size_t plane_off = (size_t)k * PLANE;        // within a [K][H][W] frame

    if (tid < KCH) WfS[tid] = Wf[k * KCH + tid];
    if (tid == 0) { sb[0] = ld_acq(&g_bar_gen[n]); sb[1] = ld_acq(&g_flags[b]); }

    const float bf_k = bf[k];
    const float bs_k = bs[k];
    const float inh  = Ws[k * 841];                 // uniform inhibition value
    const float emin = Ws[k * 841 + 420] - inh;     // center excitation minus inh

    // zero both R buffers + H29 + H9 (X_0 = 0; edge rows stay zero forever)
    for (int i = tid; i < 4 * ROWS_L * RP; i += NTHR) sm[i] = 0.f;

    // ---- feat mapping: (row rr_f, 4 contiguous pixels) ----
    const int rr_f = tid >> 4;                 // 0..31
    const int w0_f = (tid & 15) << 2;
    const float4 inb4 = *(const float4*)(inbound + (size_t)(n * KCH + k) * PLANE
                                         + (r0 + rr_f) * HW + w0_f);
    const float base0 = 0.5f * inb4.x + bf_k;
    const float base1 = 0.5f * inb4.y + bf_k;
    const float base2 = 0.5f * inb4.z + bf_k;
    const float base3 = 0.5f * inb4.w + bf_k;
    *(float4*)&S[rr_f * HW + w0_f] = make_float4(base0, base1, base2, base3);

    // ---- partner-halo mapping: 14 rows x 16 float4 = 224 items ----
    // h=0: global rows 32..45 -> j=46..59 ; h=1: global rows 18..31 -> j=0..13
    const int pj0 = h ? 0 : 46;
    const int pg0 = h ? 18 : 32;
    const int jr  = tid >> 4;                  // valid for tid<224
    const int wq  = (tid & 15) << 2;

    // ---- H mapping ----
    const int j_h = tid >> 3;                  // 0..63 (active <60)
    const int s_h = (tid & 7) << 3;

    // ---- V mapping: 512 threads, (column, 4-row segment) ----
    const int w_v = tid & 63;
    const int rb  = (tid >> 6) << 2;

    __syncthreads();
    const unsigned gen0 = sb[0], fbase = sb[1];

    for (int t = 0; t < TSTEPS; t++) {
        float* R_cur = (t & 1) ? Rb1 : Rb0;
        float* R_nxt = (t & 1) ? Rb0 : Rb1;
        // frames: X_t = out[n, t-1], X_{t+1} = out[n, t]
        const float* frame_prev = out + ((size_t)(n * TSTEPS + t - 1) * KCH) * PLANE;
        float*       frame_cur  = out + ((size_t)(n * TSTEPS + t)     * KCH) * PLANE;

        // ======== feat (t>0): S = base + Wf @ X_t ========
        if (t > 0) {
            const float4* bp = (const float4*)(frame_prev + (r0 + rr_f) * HW + w0_f);
            float a0 = base0, a1 = base1, a2 = base2, a3 = base3;
            #pragma unroll
            for (int i = 0; i < KCH; i++) {
                const float wv = WfS[i];
                const float4 x = bp[i * (PLANE / 4)];
                a0 += wv * x.x; a1 += wv * x.y;
                a2 += wv * x.z; a3 += wv * x.w;
            }
            *(float4*)&S[rr_f * HW + w0_f] = make_float4(a0, a1, a2, a3);
            __syncthreads();
        }

        // ======== V: vertical box sums (H from previous tail) + combine ========
        {
            float b29a = 0.f, b29b = 0.f, b9 = 0.f;
            #pragma unroll
            for (int d = 0; d < 14; d++) {
                b29a += H29[(rb + d) * RP + w_v];
                b29b += H29[(rb + 14 + d) * RP + w_v];
            }
            float b29 = b29a + b29b + H29[(rb + 28) * RP + w_v];
            #pragma unroll
            for (int d = 0; d < 9; d++) b9 += H9[(rb + 10 + d) * RP + w_v];

            #pragma unroll
            for (int r = 0; r < 4; r++) {
                const int rr = rb + r;
                const int j  = rr + 14;
                if (r > 0) {
                    b29 += H29[(rr + 28) * RP + w_v] - H29[(rr - 1) * RP + w_v];
                    b9  += H9 [(j + 4)  * RP + w_v] - H9 [(j - 5)  * RP + w_v];
                }
                const float sp = inh * b29 + emin * b9 + bs_k;
                const float xo = R_cur[j * RP + w_v];
                const float xn = 0.8f * xo + 0.2f * fmaxf(S[rr * HW + w_v] + sp, 0.f);
                R_nxt[j * RP + w_v] = xn;                  // interior rows for t+1
                frame_cur[plane_off + (size_t)(r0 + rr) * HW + w_v] = xn;
            }
        }

        if (t == TSTEPS - 1) break;

        __syncthreads();                       // out/R_nxt stores + smem reads done
        const unsigned ftgt = fbase + (unsigned)t + 1u;
        const unsigned gtgt = gen0  + (unsigned)t + 1u;
        if (tid == 0) {
            __threadfence();                   // publish this CTA's out stores
            st_rel(&g_flags[b], ftgt);
            if (atomicAdd(&g_bar_cnt[n], 1u) == NCTA_B - 1) {
                g_bar_cnt[n] = 0;
                st_rel(&g_bar_gen[n], gtgt);
            }
            // wait only for partner before touching its halo rows
            while ((int)(ld_acq(&g_flags[partner]) - ftgt) < 0) { }
        }
        __syncthreads();

        // ======== partner halo rows of X_{t+1} -> R_nxt (barrier shadow) ========
        if (tid < 224) {
            const float4 v = *(const float4*)(frame_cur + plane_off
                                              + (pg0 + jr) * HW + wq);
            float* rp = &R_nxt[(pj0 + jr) * RP + wq];
            rp[0] = v.x; rp[1] = v.y; rp[2] = v.z; rp[3] = v.w;
        }
        __syncthreads();

        // ======== H for step t+1 from R_nxt (barrier shadow) ========
        if (j_h < ROWS_L) {
            float v[36];
            const float* row = &R_nxt[j_h * RP];
            #pragma unroll
            for (int d = 0; d < 36; d++) {
                const int w = s_h - 14 + d;
                v[d] = (w >= 0 && w < HW) ? row[w] : 0.f;
            }
            float sa = 0.f, sc = 0.f;
            #pragma unroll
            for (int d = 0; d < 14; d++) { sa += v[d]; sc += v[d + 14]; }
            float s29 = sa + sc + v[28];
            H29[j_h * RP + s_h] = s29;
            #pragma unroll
            for (int p = 1; p < 8; p++) {
                s29 += v[p + 28] - v[p - 1];
                H29[j_h * RP + s_h + p] = s29;
            }
            float s9 = 0.f;
            #pragma unroll
            for (int d = 10; d < 19; d++) s9 += v[d];
            H9[j_h * RP + s_h] = s9;
            #pragma unroll
            for (int p = 1; p < 8; p++) {
                s9 += v[p + 18] - v[p + 9];
                H9[j_h * RP + s_h + p] = s9;
            }
        }

        // batch-barrier wait (mostly satisfied — hidden behind halo + H work)
        if (tid == 0) {
            while ((int)(ld_acq(&g_bar_gen[n]) - gtgt) < 0) { }
        }
        __syncthreads();
    }
}

extern "C" void kernel_launch(void* const* d_in, const int* in_sizes, int n_in,
                              void* d_out, int out_size)
{
    const float* inbound = (const float*)d_in[0];
    const float* Wf      = (const float*)d_in[1];
    const float* bf      = (const float*)d_in[2];
    const float* Ws      = (const float*)d_in[3];
    const float* bs      = (const float*)d_in[4];
    float* out = (float*)d_out;

    const int smem_bytes = (4 * ROWS_L * RP + 32 * HW + KCH) * sizeof(float) + 16;
    static bool attr_set = false;
    if (!attr_set) {
        cudaFuncSetAttribute(persist_kernel,
                             cudaFuncAttributeMaxDynamicSharedMemorySize, smem_bytes);
        attr_set = true;
    }
    persist_kernel<<<NCTA, NTHR, smem_bytes>>>(inbound, Wf, bf, Ws, bs, out);
}